// round 1
// baseline (speedup 1.0000x reference)
#include <cuda_runtime.h>
#include <stdint.h>

typedef unsigned long long ull;

// ---------------- packed f32x2 helpers (sm_103a) ----------------
__device__ __forceinline__ ull fma2(ull a, ull b, ull c) {
    ull d;
    asm("fma.rn.f32x2 %0, %1, %2, %3;" : "=l"(d) : "l"(a), "l"(b), "l"(c));
    return d;
}
__device__ __forceinline__ ull mul2(ull a, ull b) {
    ull d;
    asm("mul.rn.f32x2 %0, %1, %2;" : "=l"(d) : "l"(a), "l"(b));
    return d;
}
__device__ __forceinline__ ull add2(ull a, ull b) {
    ull d;
    asm("add.rn.f32x2 %0, %1, %2;" : "=l"(d) : "l"(a), "l"(b));
    return d;
}
__device__ __forceinline__ ull pk2(float lo, float hi) {
    ull r;
    asm("mov.b64 %0, {%1, %2};" : "=l"(r) : "f"(lo), "f"(hi));
    return r;
}
__device__ __forceinline__ void upk2(ull v, float& lo, float& hi) {
    asm("mov.b64 {%0, %1}, %2;" : "=f"(lo), "=f"(hi) : "l"(v));
}
__device__ __forceinline__ ull dupf(float v) {
    union { float f[2]; ull u; } t;
    t.f[0] = v; t.f[1] = v;
    return t.u;
}

// leaky relu slope (RReLU eval mode): a = 0.0025
// f(x) = c1*x + c2*|x|,  c1=(1+a)/2, c2=(1-a)/2  (branch-free, packed)
#define SLOPE_A 0.0025f
__device__ __forceinline__ ull lrelu2(ull x, ull c1p, ull c2p) {
    ull ax = x & 0x7FFFFFFF7FFFFFFFULL;      // |x| on both halves
    return fma2(x, c1p, mul2(ax, c2p));
}

// ---------------- layer table ----------------
// layers: in(8,8) h1(8,4) h2(4,4) h3(4,4) h4(4,4) h5(4,4) enc(4,1)
//         h6(1,4) h7(4,4) h8(4,4) h9(4,4) h10(4,4) dec(4,8)
// shared layout per layer: [FO biases][FI*FO weights], each as (w,w) ull
#define OFF_IN   0
#define OFF_H1   72
#define OFF_H2   108
#define OFF_H3   128
#define OFF_H4   148
#define OFF_H5   168
#define OFF_ENC  188
#define OFF_H6   193
#define OFF_H7   201
#define OFF_H8   221
#define OFF_H9   241
#define OFF_H10  261
#define OFF_DEC  281
#define SW_TOTAL 321

struct PP {
    const float* W[13];
    const float* B[13];
};

// fill one layer's packed params into shared (cooperative, per block)
__device__ __forceinline__ void fillL(ull* s, int base, const float* W, const float* B,
                                      int FI, int FO, int tid, int nt) {
    for (int j = tid; j < FO; j += nt)       s[base + j]       = dupf(B[j]);
    for (int k = tid; k < FI * FO; k += nt)  s[base + FO + k]  = dupf(W[k]);
}

// dense layer on two row-pairs, one LDS.64 per weight shared by both pairs
template <int FI, int FO>
__device__ __forceinline__ void dense2(const ull* __restrict__ s, int off,
                                       const ull* xa, const ull* xb,
                                       ull* ya, ull* yb) {
#pragma unroll
    for (int j = 0; j < FO; ++j) {
        ull bb = s[off + j];
        ya[j] = bb; yb[j] = bb;
    }
#pragma unroll
    for (int i = 0; i < FI; ++i) {
        ull xai = xa[i], xbi = xb[i];
#pragma unroll
        for (int j = 0; j < FO; ++j) {
            ull w = s[off + FO + i * FO + j];
            ya[j] = fma2(xai, w, ya[j]);
            yb[j] = fma2(xbi, w, yb[j]);
        }
    }
}

template <int NV>
__device__ __forceinline__ void lreluN(ull* v, ull c1p, ull c2p) {
#pragma unroll
    for (int i = 0; i < NV; ++i) v[i] = lrelu2(v[i], c1p, c2p);
}

__global__ __launch_bounds__(256)
void ann_net_kernel(const float* __restrict__ x_in, PP pp,
                    float* __restrict__ out, int N) {
    __shared__ ull s[SW_TOTAL];
    const int tid = threadIdx.x;
    const int nt  = blockDim.x;

    fillL(s, OFF_IN,  pp.W[0],  pp.B[0],  8, 8, tid, nt);
    fillL(s, OFF_H1,  pp.W[1],  pp.B[1],  8, 4, tid, nt);
    fillL(s, OFF_H2,  pp.W[2],  pp.B[2],  4, 4, tid, nt);
    fillL(s, OFF_H3,  pp.W[3],  pp.B[3],  4, 4, tid, nt);
    fillL(s, OFF_H4,  pp.W[4],  pp.B[4],  4, 4, tid, nt);
    fillL(s, OFF_H5,  pp.W[5],  pp.B[5],  4, 4, tid, nt);
    fillL(s, OFF_ENC, pp.W[6],  pp.B[6],  4, 1, tid, nt);
    fillL(s, OFF_H6,  pp.W[7],  pp.B[7],  1, 4, tid, nt);
    fillL(s, OFF_H7,  pp.W[8],  pp.B[8],  4, 4, tid, nt);
    fillL(s, OFF_H8,  pp.W[9],  pp.B[9],  4, 4, tid, nt);
    fillL(s, OFF_H9,  pp.W[10], pp.B[10], 4, 4, tid, nt);
    fillL(s, OFF_H10, pp.W[11], pp.B[11], 4, 4, tid, nt);
    fillL(s, OFF_DEC, pp.W[12], pp.B[12], 4, 8, tid, nt);
    __syncthreads();

    const ull C1P = dupf(0.5f * (1.0f + SLOPE_A));
    const ull C2P = dupf(0.5f * (1.0f - SLOPE_A));

    const int gtid = blockIdx.x * blockDim.x + tid;
    const int T = (N + 3) >> 2;       // rows per "slot"
    if (gtid >= T) return;

    const int r0 = gtid;
    const int r1 = gtid + T;
    const int r2 = gtid + 2 * T;
    const int r3 = gtid + 3 * T;
    const bool v1 = r1 < N, v2 = r2 < N, v3 = r3 < N;
    const int l1 = v1 ? r1 : 0, l2 = v2 ? r2 : 0, l3 = v3 ? r3 : 0;

    // ---- load 4 rows (8 floats each), coalesced across lanes ----
    const float4* in4 = reinterpret_cast<const float4*>(x_in);
    float4 a0 = in4[2 * r0], a1 = in4[2 * r0 + 1];
    float4 b0 = in4[2 * l1], b1 = in4[2 * l1 + 1];
    float4 c0 = in4[2 * l2], c1 = in4[2 * l2 + 1];
    float4 d0 = in4[2 * l3], d1 = in4[2 * l3 + 1];

    // pair A = rows (r0, r1); pair B = rows (r2, r3)
    ull xa8[8], xb8[8];
    xa8[0] = pk2(a0.x, b0.x); xa8[1] = pk2(a0.y, b0.y);
    xa8[2] = pk2(a0.z, b0.z); xa8[3] = pk2(a0.w, b0.w);
    xa8[4] = pk2(a1.x, b1.x); xa8[5] = pk2(a1.y, b1.y);
    xa8[6] = pk2(a1.z, b1.z); xa8[7] = pk2(a1.w, b1.w);
    xb8[0] = pk2(c0.x, d0.x); xb8[1] = pk2(c0.y, d0.y);
    xb8[2] = pk2(c0.z, d0.z); xb8[3] = pk2(c0.w, d0.w);
    xb8[4] = pk2(c1.x, d1.x); xb8[5] = pk2(c1.y, d1.y);
    xb8[6] = pk2(c1.z, d1.z); xb8[7] = pk2(c1.w, d1.w);

    // ---- network ----
    ull ta8[8], tb8[8];
    dense2<8, 8>(s, OFF_IN, xa8, xb8, ta8, tb8);
    lreluN<8>(ta8, C1P, C2P); lreluN<8>(tb8, C1P, C2P);

    ull x4a[4], x4b[4];
    dense2<8, 4>(s, OFF_H1, ta8, tb8, x4a, x4b);

    {   // residual block h2/h3
        ull ta[4], tb[4], ua[4], ub[4];
        dense2<4, 4>(s, OFF_H2, x4a, x4b, ta, tb);
        lreluN<4>(ta, C1P, C2P); lreluN<4>(tb, C1P, C2P);
        dense2<4, 4>(s, OFF_H3, ta, tb, ua, ub);
#pragma unroll
        for (int j = 0; j < 4; ++j) { x4a[j] = add2(x4a[j], ua[j]); x4b[j] = add2(x4b[j], ub[j]); }
    }
    {   // residual block h4/h5
        ull ta[4], tb[4], ua[4], ub[4];
        dense2<4, 4>(s, OFF_H4, x4a, x4b, ta, tb);
        lreluN<4>(ta, C1P, C2P); lreluN<4>(tb, C1P, C2P);
        dense2<4, 4>(s, OFF_H5, ta, tb, ua, ub);
#pragma unroll
        for (int j = 0; j < 4; ++j) { x4a[j] = add2(x4a[j], ua[j]); x4b[j] = add2(x4b[j], ub[j]); }
    }

    // encode (4->1) + rrelu
    ull ea[1], eb[1];
    dense2<4, 1>(s, OFF_ENC, x4a, x4b, ea, eb);
    ea[0] = lrelu2(ea[0], C1P, C2P);
    eb[0] = lrelu2(eb[0], C1P, C2P);

    // h6 (1->4) + rrelu
    ull y4a[4], y4b[4];
    dense2<1, 4>(s, OFF_H6, ea, eb, y4a, y4b);
    lreluN<4>(y4a, C1P, C2P); lreluN<4>(y4b, C1P, C2P);

    {   // residual block h7/h8
        ull ta[4], tb[4], ua[4], ub[4];
        dense2<4, 4>(s, OFF_H7, y4a, y4b, ta, tb);
        lreluN<4>(ta, C1P, C2P); lreluN<4>(tb, C1P, C2P);
        dense2<4, 4>(s, OFF_H8, ta, tb, ua, ub);
#pragma unroll
        for (int j = 0; j < 4; ++j) { y4a[j] = add2(y4a[j], ua[j]); y4b[j] = add2(y4b[j], ub[j]); }
    }
    {   // residual block h9/h10
        ull ta[4], tb[4], ua[4], ub[4];
        dense2<4, 4>(s, OFF_H9, y4a, y4b, ta, tb);
        lreluN<4>(ta, C1P, C2P); lreluN<4>(tb, C1P, C2P);
        dense2<4, 4>(s, OFF_H10, ta, tb, ua, ub);
#pragma unroll
        for (int j = 0; j < 4; ++j) { y4a[j] = add2(y4a[j], ua[j]); y4b[j] = add2(y4b[j], ub[j]); }
    }

    // decode (4->8) + rrelu
    ull da[8], db[8];
    dense2<4, 8>(s, OFF_DEC, y4a, y4b, da, db);
    lreluN<8>(da, C1P, C2P); lreluN<8>(db, C1P, C2P);

    // ---- stores ----
    // output layout: [0, N) = x_encode flattened, [N, 9N) = x_decode flattened
    {
        float e0, e1, e2, e3;
        upk2(ea[0], e0, e1);
        upk2(eb[0], e2, e3);
        out[r0] = e0;
        if (v1) out[r1] = e1;
        if (v2) out[r2] = e2;
        if (v3) out[r3] = e3;
    }

    float la[8], ha[8], lb[8], hb[8];
#pragma unroll
    for (int j = 0; j < 8; ++j) { upk2(da[j], la[j], ha[j]); upk2(db[j], lb[j], hb[j]); }

    if ((N & 3) == 0) {
        float4* od = reinterpret_cast<float4*>(out + N);
        od[2 * r0]     = make_float4(la[0], la[1], la[2], la[3]);
        od[2 * r0 + 1] = make_float4(la[4], la[5], la[6], la[7]);
        if (v1) {
            od[2 * r1]     = make_float4(ha[0], ha[1], ha[2], ha[3]);
            od[2 * r1 + 1] = make_float4(ha[4], ha[5], ha[6], ha[7]);
        }
        if (v2) {
            od[2 * r2]     = make_float4(lb[0], lb[1], lb[2], lb[3]);
            od[2 * r2 + 1] = make_float4(lb[4], lb[5], lb[6], lb[7]);
        }
        if (v3) {
            od[2 * r3]     = make_float4(hb[0], hb[1], hb[2], hb[3]);
            od[2 * r3 + 1] = make_float4(hb[4], hb[5], hb[6], hb[7]);
        }
    } else {
        float* od = out + N;
#pragma unroll
        for (int j = 0; j < 8; ++j) {
            od[(size_t)r0 * 8 + j] = la[j];
            if (v1) od[(size_t)r1 * 8 + j] = ha[j];
            if (v2) od[(size_t)r2 * 8 + j] = lb[j];
            if (v3) od[(size_t)r3 * 8 + j] = hb[j];
        }
    }
}

extern "C" void kernel_launch(void* const* d_in, const int* in_sizes, int n_in,
                              void* d_out, int out_size) {
    const float* x_in = (const float*)d_in[0];
    PP pp;
    for (int l = 0; l < 13; ++l) {
        pp.W[l] = (const float*)d_in[1 + 2 * l];
        pp.B[l] = (const float*)d_in[2 + 2 * l];
    }
    const int N = in_sizes[0] / 8;       // number of rows
    const int T = (N + 3) / 4;           // threads needed (4 rows/thread)
    const int blocks = (T + 255) / 256;
    ann_net_kernel<<<blocks, 256>>>(x_in, pp, (float*)d_out, N);
}